// round 1
// baseline (speedup 1.0000x reference)
#include <cuda_runtime.h>
#include <math_constants.h>
#include <stdint.h>

// Problem constants (shapes fixed by the reference).
#define MAX_N 100032
#define MAX_E 1600000
#define D_IN  128
#define D_OUT 64

// ---------------- Scratch (static __device__ globals; no runtime allocs) ---
__device__ int   g_flag;                    // 1 => edge_index is int64, 0 => int32
__device__ int   g_src[MAX_E];
__device__ int   g_dst[MAX_E];
__device__ int   g_csr[MAX_E];              // src indices grouped by dst
__device__ int   g_deg[MAX_N];
__device__ int   g_off[MAX_N + 1];
__device__ int   g_cur[MAX_N];
__device__ float g_agg[(size_t)MAX_N * D_IN];   // 51.2 MB

// ---------------- K0: detect edge_index dtype ------------------------------
// If int64 (little-endian), all odd 32-bit words of in-range indices are 0.
__global__ void k_detect(const unsigned int* __restrict__ w) {
    unsigned int v = 0;
    for (int i = threadIdx.x * 2 + 1; i < 512; i += 64) v |= w[i];
    v = __reduce_or_sync(0xffffffffu, v);
    if (threadIdx.x == 0) g_flag = (v == 0u) ? 1 : 0;
}

// ---------------- K1: zero degree histogram --------------------------------
__global__ void k_zero(int n) {
    int i = blockIdx.x * blockDim.x + threadIdx.x;
    if (i < n) g_deg[i] = 0;
}

// ---------------- K2: normalize edges to int32 + histogram -----------------
__global__ void k_count(const void* __restrict__ ei, int E) {
    int e = blockIdx.x * blockDim.x + threadIdx.x;
    if (e >= E) return;
    int s, d;
    if (g_flag) {
        const long long* p = (const long long*)ei;
        s = (int)p[e];
        d = (int)p[(size_t)E + e];
    } else {
        const int* p = (const int*)ei;
        s = p[e];
        d = p[E + e];
    }
    g_src[e] = s;
    g_dst[e] = d;
    atomicAdd(&g_deg[d], 1);
}

// ---------------- K3: single-block exclusive scan of degrees ---------------
__global__ void k_scan(int n) {
    __shared__ int sums[1024];
    int t = threadIdx.x;
    int chunk = (n + 1023) >> 10;
    int s0 = t * chunk;
    int s1 = min(s0 + chunk, n);
    int s = 0;
    for (int i = s0; i < s1; i++) s += g_deg[i];
    sums[t] = s;
    __syncthreads();
    // Kogge-Stone inclusive scan
    for (int d = 1; d < 1024; d <<= 1) {
        int v = (t >= d) ? sums[t - d] : 0;
        __syncthreads();
        sums[t] += v;
        __syncthreads();
    }
    int run = (t == 0) ? 0 : sums[t - 1];
    for (int i = s0; i < s1; i++) {
        g_off[i] = run;
        g_cur[i] = run;
        run += g_deg[i];
    }
    if (t == 0) g_off[n] = sums[1023];
}

// ---------------- K4: scatter src into CSR buckets -------------------------
__global__ void k_scatter(int E) {
    int e = blockIdx.x * blockDim.x + threadIdx.x;
    if (e >= E) return;
    int d = g_dst[e];
    int pos = atomicAdd(&g_cur[d], 1);
    g_csr[pos] = g_src[e];
}

// ---------------- K5: gather-max aggregation (warp per node) ---------------
__global__ void k_agg(const float* __restrict__ x, int N) {
    int gt = blockIdx.x * blockDim.x + threadIdx.x;
    int w = gt >> 5;
    int lane = gt & 31;
    if (w >= N) return;
    int beg = g_off[w];
    int end = g_off[w + 1];

    float4 acc = make_float4(-CUDART_INF_F, -CUDART_INF_F, -CUDART_INF_F, -CUDART_INF_F);
    const float4* xv = (const float4*)x;

    int e = beg;
    for (; e + 1 < end; e += 2) {
        int s0 = g_csr[e];
        int s1 = g_csr[e + 1];
        float4 v0 = xv[(size_t)s0 * 32 + lane];
        float4 v1 = xv[(size_t)s1 * 32 + lane];
        acc.x = fmaxf(acc.x, fmaxf(v0.x, v1.x));
        acc.y = fmaxf(acc.y, fmaxf(v0.y, v1.y));
        acc.z = fmaxf(acc.z, fmaxf(v0.z, v1.z));
        acc.w = fmaxf(acc.w, fmaxf(v0.w, v1.w));
    }
    if (e < end) {
        int s0 = g_csr[e];
        float4 v0 = xv[(size_t)s0 * 32 + lane];
        acc.x = fmaxf(acc.x, v0.x);
        acc.y = fmaxf(acc.y, v0.y);
        acc.z = fmaxf(acc.z, v0.z);
        acc.w = fmaxf(acc.w, v0.w);
    }
    if (beg == end) acc = make_float4(0.f, 0.f, 0.f, 0.f);
    ((float4*)g_agg)[(size_t)w * 32 + lane] = acc;
}

// ---------------- K6: fused GEMM (K=256 concat) + bias + log_softmax -------
// out[n][c] = logsoftmax_c( sum_k agg[n][k]*Wl[c][k] + bl[c] + sum_k x[n][k]*Wr[c][k] )
// Block: 64 nodes x 64 outputs, 256 threads, 4x4 microtiles, TK=32.
__global__ __launch_bounds__(256) void k_gemm(const float* __restrict__ x,
                                              const float* __restrict__ Wl,
                                              const float* __restrict__ bl,
                                              const float* __restrict__ Wr,
                                              float* __restrict__ out, int N) {
    __shared__ float As[32][65];  // [kk][node]
    __shared__ float Bs[32][65];  // [kk][c]

    int t = threadIdx.x;
    int tx = t & 15;      // output group (4 outs)
    int ty = t >> 4;      // node group (4 nodes)
    int nb = blockIdx.x * 64;

    float acc[4][4];
#pragma unroll
    for (int i = 0; i < 4; i++)
#pragma unroll
        for (int j = 0; j < 4; j++) acc[i][j] = 0.f;

    int kq = (t & 7) * 4;   // k offset within chunk (0..28)
    int row = t >> 3;       // 0..31

    for (int kb = 0; kb < 256; kb += 32) {
        const float* Asrc = (kb < 128) ? (g_agg + kb) : (x + (kb - 128));
        const float* Wsrc = (kb < 128) ? (Wl + kb) : (Wr + (kb - 128));

#pragma unroll
        for (int r2 = 0; r2 < 2; r2++) {
            int n = nb + row + r2 * 32;
            float4 v = (n < N) ? *(const float4*)(Asrc + (size_t)n * D_IN + kq)
                               : make_float4(0.f, 0.f, 0.f, 0.f);
            As[kq + 0][row + r2 * 32] = v.x;
            As[kq + 1][row + r2 * 32] = v.y;
            As[kq + 2][row + r2 * 32] = v.z;
            As[kq + 3][row + r2 * 32] = v.w;

            int c = row + r2 * 32;
            float4 wv = *(const float4*)(Wsrc + (size_t)c * D_IN + kq);
            Bs[kq + 0][c] = wv.x;
            Bs[kq + 1][c] = wv.y;
            Bs[kq + 2][c] = wv.z;
            Bs[kq + 3][c] = wv.w;
        }
        __syncthreads();

#pragma unroll
        for (int kk = 0; kk < 32; kk++) {
            float a0 = As[kk][ty * 4 + 0];
            float a1 = As[kk][ty * 4 + 1];
            float a2 = As[kk][ty * 4 + 2];
            float a3 = As[kk][ty * 4 + 3];
            float b0 = Bs[kk][tx * 4 + 0];
            float b1 = Bs[kk][tx * 4 + 1];
            float b2 = Bs[kk][tx * 4 + 2];
            float b3 = Bs[kk][tx * 4 + 3];
            acc[0][0] += a0 * b0; acc[0][1] += a0 * b1; acc[0][2] += a0 * b2; acc[0][3] += a0 * b3;
            acc[1][0] += a1 * b0; acc[1][1] += a1 * b1; acc[1][2] += a1 * b2; acc[1][3] += a1 * b3;
            acc[2][0] += a2 * b0; acc[2][1] += a2 * b1; acc[2][2] += a2 * b2; acc[2][3] += a2 * b3;
            acc[3][0] += a3 * b0; acc[3][1] += a3 * b1; acc[3][2] += a3 * b2; acc[3][3] += a3 * b3;
        }
        __syncthreads();
    }

    // bias
    float bv[4];
#pragma unroll
    for (int j = 0; j < 4; j++) bv[j] = bl[tx * 4 + j];
#pragma unroll
    for (int i = 0; i < 4; i++)
#pragma unroll
        for (int j = 0; j < 4; j++) acc[i][j] += bv[j];

    // log_softmax per node row: the 64 outputs of node (nb + ty*4 + i) are
    // held by the 16 lanes sharing this ty (one half-warp) -> shfl_xor 1,2,4,8.
#pragma unroll
    for (int i = 0; i < 4; i++) {
        float m = acc[i][0];
        m = fmaxf(m, acc[i][1]);
        m = fmaxf(m, acc[i][2]);
        m = fmaxf(m, acc[i][3]);
#pragma unroll
        for (int o = 8; o >= 1; o >>= 1)
            m = fmaxf(m, __shfl_xor_sync(0xffffffffu, m, o));
        float s = expf(acc[i][0] - m) + expf(acc[i][1] - m) +
                  expf(acc[i][2] - m) + expf(acc[i][3] - m);
#pragma unroll
        for (int o = 8; o >= 1; o >>= 1)
            s += __shfl_xor_sync(0xffffffffu, s, o);
        float lse = m + logf(s);

        int n = nb + ty * 4 + i;
        if (n < N) {
            float4 o4 = make_float4(acc[i][0] - lse, acc[i][1] - lse,
                                    acc[i][2] - lse, acc[i][3] - lse);
            *(float4*)(out + (size_t)n * D_OUT + tx * 4) = o4;
        }
    }
}

// ---------------- launcher -------------------------------------------------
extern "C" void kernel_launch(void* const* d_in, const int* in_sizes, int n_in,
                              void* d_out, int out_size) {
    const float* x  = (const float*)d_in[0];
    const void*  ei = d_in[1];
    const float* Wl = (const float*)d_in[2];
    const float* bl = (const float*)d_in[3];
    const float* Wr = (const float*)d_in[4];
    float* out = (float*)d_out;

    int N = in_sizes[0] / D_IN;
    int E = in_sizes[1] / 2;

    k_detect<<<1, 32>>>((const unsigned int*)ei);
    k_zero<<<(N + 255) / 256, 256>>>(N);
    k_count<<<(E + 255) / 256, 256>>>(ei, E);
    k_scan<<<1, 1024>>>(N);
    k_scatter<<<(E + 255) / 256, 256>>>(E);
    k_agg<<<(N * 32 + 255) / 256, 256>>>(x, N);
    k_gemm<<<(N + 63) / 64, 256>>>(x, Wl, bl, Wr, out, N);
}

// round 3
// speedup vs baseline: 1.7016x; 1.7016x over previous
#include <cuda_runtime.h>
#include <math_constants.h>
#include <stdint.h>

// Problem constants (shapes fixed by the reference).
#define MAX_N 100032
#define MAX_E 1600000
#define D_IN  128
#define D_OUT 64

// ---------------- Scratch (static __device__ globals; no runtime allocs) ---
__device__ int   g_flag;                    // 1 => edge_index is int64, 0 => int32
__device__ int   g_src[MAX_E];
__device__ int   g_dst[MAX_E];
__device__ int   g_csr[MAX_E];              // src indices grouped by dst
__device__ int   g_deg[MAX_N];
__device__ int   g_off[MAX_N + 1];
__device__ int   g_cur[MAX_N];
__device__ int   g_bsum[128];
__device__ float g_agg[(size_t)MAX_N * D_IN];   // 51.2 MB

// ---------------- K0: detect edge_index dtype ------------------------------
// If int64 (little-endian), all odd 32-bit words of in-range indices are 0.
__global__ void k_detect(const unsigned int* __restrict__ w) {
    unsigned int v = 0;
    for (int i = threadIdx.x * 2 + 1; i < 512; i += 64) v |= w[i];
    v = __reduce_or_sync(0xffffffffu, v);
    if (threadIdx.x == 0) g_flag = (v == 0u) ? 1 : 0;
}

// ---------------- K1: zero degree histogram --------------------------------
__global__ void k_zero(int n) {
    int i = blockIdx.x * blockDim.x + threadIdx.x;
    if (i < n) g_deg[i] = 0;
}

// ---------------- K2: normalize edges to int32 + histogram -----------------
__global__ void k_count(const void* __restrict__ ei, int E) {
    int e = blockIdx.x * blockDim.x + threadIdx.x;
    if (e >= E) return;
    int s, d;
    if (g_flag) {
        const long long* p = (const long long*)ei;
        s = (int)p[e];
        d = (int)p[(size_t)E + e];
    } else {
        const int* p = (const int*)ei;
        s = p[e];
        d = p[E + e];
    }
    g_src[e] = s;
    g_dst[e] = d;
    atomicAdd(&g_deg[d], 1);
}

// ---------------- K3a: per-block exclusive scan (1024 elems/block) ---------
__global__ __launch_bounds__(1024) void k_scan1(int n) {
    __shared__ int wsum[32];
    int t = threadIdx.x;
    int i = blockIdx.x * 1024 + t;
    int lane = t & 31;
    int wid = t >> 5;

    int d = (i < n) ? g_deg[i] : 0;
    // warp inclusive scan
    int inc = d;
#pragma unroll
    for (int o = 1; o < 32; o <<= 1) {
        int v = __shfl_up_sync(0xffffffffu, inc, o);
        if (lane >= o) inc += v;
    }
    if (lane == 31) wsum[wid] = inc;
    __syncthreads();
    if (wid == 0) {
        int s = wsum[lane];
        int si = s;
#pragma unroll
        for (int o = 1; o < 32; o <<= 1) {
            int v = __shfl_up_sync(0xffffffffu, si, o);
            if (lane >= o) si += v;
        }
        wsum[lane] = si - s;   // exclusive warp prefix
        if (lane == 31 && blockIdx.x < 128) g_bsum[blockIdx.x] = si;
    }
    __syncthreads();
    if (i < n) g_off[i] = inc - d + wsum[wid];   // block-local exclusive
}

// ---------------- K3b: scan the block sums (1 small block) -----------------
__global__ void k_scan2(int nb) {
    __shared__ int wsum[4];
    int t = threadIdx.x;   // 128 threads
    int lane = t & 31;
    int wid = t >> 5;
    int d = (t < nb) ? g_bsum[t] : 0;
    int inc = d;
#pragma unroll
    for (int o = 1; o < 32; o <<= 1) {
        int v = __shfl_up_sync(0xffffffffu, inc, o);
        if (lane >= o) inc += v;
    }
    if (lane == 31) wsum[wid] = inc;
    __syncthreads();
    int pre = 0;
    for (int wprev = 0; wprev < wid; wprev++) pre += wsum[wprev];
    if (t < nb) g_bsum[t] = inc - d + pre;   // exclusive
}

// ---------------- K3c: add block offsets, replicate to g_cur ---------------
__global__ void k_scan3(int n, int E) {
    int i = blockIdx.x * blockDim.x + threadIdx.x;
    if (i < n) {
        int off = g_off[i] + g_bsum[i >> 10];
        g_off[i] = off;
        g_cur[i] = off;
    }
    if (i == 0) g_off[n] = E;
}

// ---------------- K4: scatter src into CSR buckets -------------------------
__global__ void k_scatter(int E) {
    int e = blockIdx.x * blockDim.x + threadIdx.x;
    if (e >= E) return;
    int d = g_dst[e];
    int pos = atomicAdd(&g_cur[d], 1);
    g_csr[pos] = g_src[e];
}

// ---------------- K5: gather-max aggregation (warp per node) ---------------
__global__ void k_agg(const float* __restrict__ x, int N) {
    int gt = blockIdx.x * blockDim.x + threadIdx.x;
    int w = gt >> 5;
    int lane = gt & 31;
    if (w >= N) return;
    int beg = g_off[w];
    int end = g_off[w + 1];

    float4 acc = make_float4(-CUDART_INF_F, -CUDART_INF_F, -CUDART_INF_F, -CUDART_INF_F);
    const float4* xv = (const float4*)x;

    int e = beg;
    for (; e + 1 < end; e += 2) {
        int s0 = g_csr[e];
        int s1 = g_csr[e + 1];
        float4 v0 = xv[(size_t)s0 * 32 + lane];
        float4 v1 = xv[(size_t)s1 * 32 + lane];
        acc.x = fmaxf(acc.x, fmaxf(v0.x, v1.x));
        acc.y = fmaxf(acc.y, fmaxf(v0.y, v1.y));
        acc.z = fmaxf(acc.z, fmaxf(v0.z, v1.z));
        acc.w = fmaxf(acc.w, fmaxf(v0.w, v1.w));
    }
    if (e < end) {
        int s0 = g_csr[e];
        float4 v0 = xv[(size_t)s0 * 32 + lane];
        acc.x = fmaxf(acc.x, v0.x);
        acc.y = fmaxf(acc.y, v0.y);
        acc.z = fmaxf(acc.z, v0.z);
        acc.w = fmaxf(acc.w, v0.w);
    }
    if (beg == end) acc = make_float4(0.f, 0.f, 0.f, 0.f);
    ((float4*)g_agg)[(size_t)w * 32 + lane] = acc;
}

// ---------------- K6: fused GEMM (K=256 concat) + bias + log_softmax -------
// out[n][c] = logsoftmax_c( sum_k agg[n][k]*Wl[c][k] + bl[c] + sum_k x[n][k]*Wr[c][k] )
// Block: 64 nodes x 64 outputs, 256 threads, 4x4 microtiles, TK=32.
__global__ __launch_bounds__(256) void k_gemm(const float* __restrict__ x,
                                              const float* __restrict__ Wl,
                                              const float* __restrict__ bl,
                                              const float* __restrict__ Wr,
                                              float* __restrict__ out, int N) {
    __shared__ float As[32][65];  // [kk][node]
    __shared__ float Bs[32][65];  // [kk][c]

    int t = threadIdx.x;
    int tx = t & 15;      // output group (4 outs)
    int ty = t >> 4;      // node group (4 nodes)
    int nb = blockIdx.x * 64;

    float acc[4][4];
#pragma unroll
    for (int i = 0; i < 4; i++)
#pragma unroll
        for (int j = 0; j < 4; j++) acc[i][j] = 0.f;

    int kq = (t & 7) * 4;   // k offset within chunk (0..28)
    int row = t >> 3;       // 0..31

    for (int kb = 0; kb < 256; kb += 32) {
        const float* Asrc = (kb < 128) ? (g_agg + kb) : (x + (kb - 128));
        const float* Wsrc = (kb < 128) ? (Wl + kb) : (Wr + (kb - 128));

#pragma unroll
        for (int r2 = 0; r2 < 2; r2++) {
            int n = nb + row + r2 * 32;
            float4 v = (n < N) ? *(const float4*)(Asrc + (size_t)n * D_IN + kq)
                               : make_float4(0.f, 0.f, 0.f, 0.f);
            As[kq + 0][row + r2 * 32] = v.x;
            As[kq + 1][row + r2 * 32] = v.y;
            As[kq + 2][row + r2 * 32] = v.z;
            As[kq + 3][row + r2 * 32] = v.w;

            int c = row + r2 * 32;
            float4 wv = *(const float4*)(Wsrc + (size_t)c * D_IN + kq);
            Bs[kq + 0][c] = wv.x;
            Bs[kq + 1][c] = wv.y;
            Bs[kq + 2][c] = wv.z;
            Bs[kq + 3][c] = wv.w;
        }
        __syncthreads();

#pragma unroll
        for (int kk = 0; kk < 32; kk++) {
            float a0 = As[kk][ty * 4 + 0];
            float a1 = As[kk][ty * 4 + 1];
            float a2 = As[kk][ty * 4 + 2];
            float a3 = As[kk][ty * 4 + 3];
            float b0 = Bs[kk][tx * 4 + 0];
            float b1 = Bs[kk][tx * 4 + 1];
            float b2 = Bs[kk][tx * 4 + 2];
            float b3 = Bs[kk][tx * 4 + 3];
            acc[0][0] += a0 * b0; acc[0][1] += a0 * b1; acc[0][2] += a0 * b2; acc[0][3] += a0 * b3;
            acc[1][0] += a1 * b0; acc[1][1] += a1 * b1; acc[1][2] += a1 * b2; acc[1][3] += a1 * b3;
            acc[2][0] += a2 * b0; acc[2][1] += a2 * b1; acc[2][2] += a2 * b2; acc[2][3] += a2 * b3;
            acc[3][0] += a3 * b0; acc[3][1] += a3 * b1; acc[3][2] += a3 * b2; acc[3][3] += a3 * b3;
        }
        __syncthreads();
    }

    // bias
    float bv[4];
#pragma unroll
    for (int j = 0; j < 4; j++) bv[j] = bl[tx * 4 + j];
#pragma unroll
    for (int i = 0; i < 4; i++)
#pragma unroll
        for (int j = 0; j < 4; j++) acc[i][j] += bv[j];

    // log_softmax per node row: the 64 outputs of node (nb + ty*4 + i) are
    // held by the 16 lanes sharing this ty (one half-warp) -> shfl_xor 1,2,4,8.
#pragma unroll
    for (int i = 0; i < 4; i++) {
        float m = acc[i][0];
        m = fmaxf(m, acc[i][1]);
        m = fmaxf(m, acc[i][2]);
        m = fmaxf(m, acc[i][3]);
#pragma unroll
        for (int o = 8; o >= 1; o >>= 1)
            m = fmaxf(m, __shfl_xor_sync(0xffffffffu, m, o));
        float s = expf(acc[i][0] - m) + expf(acc[i][1] - m) +
                  expf(acc[i][2] - m) + expf(acc[i][3] - m);
#pragma unroll
        for (int o = 8; o >= 1; o >>= 1)
            s += __shfl_xor_sync(0xffffffffu, s, o);
        float lse = m + logf(s);

        int n = nb + ty * 4 + i;
        if (n < N) {
            float4 o4 = make_float4(acc[i][0] - lse, acc[i][1] - lse,
                                    acc[i][2] - lse, acc[i][3] - lse);
            *(float4*)(out + (size_t)n * D_OUT + tx * 4) = o4;
        }
    }
}

// ---------------- launcher -------------------------------------------------
extern "C" void kernel_launch(void* const* d_in, const int* in_sizes, int n_in,
                              void* d_out, int out_size) {
    const float* x  = (const float*)d_in[0];
    const void*  ei = d_in[1];
    const float* Wl = (const float*)d_in[2];
    const float* bl = (const float*)d_in[3];
    const float* Wr = (const float*)d_in[4];
    float* out = (float*)d_out;

    int N = in_sizes[0] / D_IN;
    int E = in_sizes[1] / 2;
    int nb = (N + 1023) / 1024;

    k_detect<<<1, 32>>>((const unsigned int*)ei);
    k_zero<<<(N + 255) / 256, 256>>>(N);
    k_count<<<(E + 255) / 256, 256>>>(ei, E);
    k_scan1<<<nb, 1024>>>(N);
    k_scan2<<<1, 128>>>(nb);
    k_scan3<<<(N + 255) / 256, 256>>>(N, E);
    k_scatter<<<(E + 255) / 256, 256>>>(E);
    k_agg<<<(N * 32 + 255) / 256, 256>>>(x, N);
    k_gemm<<<(N + 63) / 64, 256>>>(x, Wl, bl, Wr, out, N);
}

// round 5
// speedup vs baseline: 1.7416x; 1.0235x over previous
#include <cuda_runtime.h>
#include <math_constants.h>
#include <stdint.h>

// Problem constants (shapes fixed by the reference).
#define MAX_N 100032
#define MAX_E 1600000
#define D_IN  128
#define D_OUT 64

// ---------------- Scratch (static __device__ globals; no runtime allocs) ---
__device__ int g_flag;                    // 1 => edge_index is int64, 0 => int32
__device__ int g_src[MAX_E];
__device__ int g_dst[MAX_E];
__device__ int g_csr[MAX_E];              // src indices grouped by dst
__device__ int g_deg[MAX_N];
__device__ int g_off[MAX_N + 1];
__device__ int g_cur[MAX_N];
__device__ int g_bsum[128];

// ---------------- K0: detect edge_index dtype ------------------------------
// If int64 (little-endian), all odd 32-bit words of in-range indices are 0.
__global__ void k_detect(const unsigned int* __restrict__ w) {
    unsigned int v = 0;
    for (int i = threadIdx.x * 2 + 1; i < 512; i += 64) v |= w[i];
    v = __reduce_or_sync(0xffffffffu, v);
    if (threadIdx.x == 0) g_flag = (v == 0u) ? 1 : 0;
}

// ---------------- K1: zero degree histogram --------------------------------
__global__ void k_zero(int n) {
    int i = blockIdx.x * blockDim.x + threadIdx.x;
    if (i < n) g_deg[i] = 0;
}

// ---------------- K2: normalize edges to int32 + histogram -----------------
__global__ void k_count(const void* __restrict__ ei, int E) {
    int e = blockIdx.x * blockDim.x + threadIdx.x;
    if (e >= E) return;
    int s, d;
    if (g_flag) {
        const long long* p = (const long long*)ei;
        s = (int)p[e];
        d = (int)p[(size_t)E + e];
    } else {
        const int* p = (const int*)ei;
        s = p[e];
        d = p[E + e];
    }
    g_src[e] = s;
    g_dst[e] = d;
    atomicAdd(&g_deg[d], 1);
}

// ---------------- K3a: per-block exclusive scan (1024 elems/block) ---------
__global__ __launch_bounds__(1024) void k_scan1(int n) {
    __shared__ int wsum[32];
    int t = threadIdx.x;
    int i = blockIdx.x * 1024 + t;
    int lane = t & 31;
    int wid = t >> 5;

    int d = (i < n) ? g_deg[i] : 0;
    int inc = d;
#pragma unroll
    for (int o = 1; o < 32; o <<= 1) {
        int v = __shfl_up_sync(0xffffffffu, inc, o);
        if (lane >= o) inc += v;
    }
    if (lane == 31) wsum[wid] = inc;
    __syncthreads();
    if (wid == 0) {
        int s = wsum[lane];
        int si = s;
#pragma unroll
        for (int o = 1; o < 32; o <<= 1) {
            int v = __shfl_up_sync(0xffffffffu, si, o);
            if (lane >= o) si += v;
        }
        wsum[lane] = si - s;   // exclusive warp prefix
        if (lane == 31 && blockIdx.x < 128) g_bsum[blockIdx.x] = si;
    }
    __syncthreads();
    if (i < n) g_off[i] = inc - d + wsum[wid];   // block-local exclusive
}

// ---------------- K3b: scan the block sums (1 small block) -----------------
__global__ void k_scan2(int nb) {
    __shared__ int wsum[4];
    int t = threadIdx.x;   // 128 threads
    int lane = t & 31;
    int wid = t >> 5;
    int d = (t < nb) ? g_bsum[t] : 0;
    int inc = d;
#pragma unroll
    for (int o = 1; o < 32; o <<= 1) {
        int v = __shfl_up_sync(0xffffffffu, inc, o);
        if (lane >= o) inc += v;
    }
    if (lane == 31) wsum[wid] = inc;
    __syncthreads();
    int pre = 0;
    for (int wprev = 0; wprev < wid; wprev++) pre += wsum[wprev];
    if (t < nb) g_bsum[t] = inc - d + pre;   // exclusive
}

// ---------------- K3c: add block offsets, replicate to g_cur ---------------
__global__ void k_scan3(int n, int E) {
    int i = blockIdx.x * blockDim.x + threadIdx.x;
    if (i < n) {
        int off = g_off[i] + g_bsum[i >> 10];
        g_off[i] = off;
        g_cur[i] = off;
    }
    if (i == 0) g_off[n] = E;
}

// ---------------- K4: scatter src into CSR buckets -------------------------
__global__ void k_scatter(int E) {
    int e = blockIdx.x * blockDim.x + threadIdx.x;
    if (e >= E) return;
    int d = g_dst[e];
    int pos = atomicAdd(&g_cur[d], 1);
    g_csr[pos] = g_src[e];
}

// ---------------- K5: fused gather-max + GEMM + bias + log_softmax ---------
// Per block: 64 nodes.
// Phase 1: 8 warps gather-max neighborhoods (8 nodes/warp) into smem
//          As_agg[k][node] (k-major, pad 65).
// Phase 2: 64x64 GEMM over K=256 ([agg | x] @ [Wl | Wr]^T): agg half is read
//          straight from smem; x half is staged into the already-consumed
//          rows of As_agg. Then bias + per-node log_softmax.
__global__ __launch_bounds__(256) void k_aggemm(const float* __restrict__ x,
                                                const float* __restrict__ Wl,
                                                const float* __restrict__ bl,
                                                const float* __restrict__ Wr,
                                                float* __restrict__ out, int N) {
    __shared__ float As_agg[128][65];
    __shared__ float Bs[32][65];

    int t = threadIdx.x;
    int w = t >> 5;
    int lane = t & 31;
    int nb = blockIdx.x * 64;

    // ---------- Phase 1: gather-max into As_agg ----------
    const float4* xv = (const float4*)x;
#pragma unroll 1
    for (int r = 0; r < 8; r++) {
        int ln = w * 8 + r;
        int n = nb + ln;
        float4 acc = make_float4(0.f, 0.f, 0.f, 0.f);
        if (n < N) {
            int beg = g_off[n];
            int end = g_off[n + 1];
            if (beg < end) {
                acc = make_float4(-CUDART_INF_F, -CUDART_INF_F,
                                  -CUDART_INF_F, -CUDART_INF_F);
                int e = beg;
                for (; e + 3 < end; e += 4) {
                    int s0 = g_csr[e];
                    int s1 = g_csr[e + 1];
                    int s2 = g_csr[e + 2];
                    int s3 = g_csr[e + 3];
                    float4 v0 = xv[(size_t)s0 * 32 + lane];
                    float4 v1 = xv[(size_t)s1 * 32 + lane];
                    float4 v2 = xv[(size_t)s2 * 32 + lane];
                    float4 v3 = xv[(size_t)s3 * 32 + lane];
                    acc.x = fmaxf(acc.x, fmaxf(fmaxf(v0.x, v1.x), fmaxf(v2.x, v3.x)));
                    acc.y = fmaxf(acc.y, fmaxf(fmaxf(v0.y, v1.y), fmaxf(v2.y, v3.y)));
                    acc.z = fmaxf(acc.z, fmaxf(fmaxf(v0.z, v1.z), fmaxf(v2.z, v3.z)));
                    acc.w = fmaxf(acc.w, fmaxf(fmaxf(v0.w, v1.w), fmaxf(v2.w, v3.w)));
                }
                for (; e < end; e++) {
                    int s0 = g_csr[e];
                    float4 v0 = xv[(size_t)s0 * 32 + lane];
                    acc.x = fmaxf(acc.x, v0.x);
                    acc.y = fmaxf(acc.y, v0.y);
                    acc.z = fmaxf(acc.z, v0.z);
                    acc.w = fmaxf(acc.w, v0.w);
                }
            }
        }
        As_agg[lane * 4 + 0][ln] = acc.x;
        As_agg[lane * 4 + 1][ln] = acc.y;
        As_agg[lane * 4 + 2][ln] = acc.z;
        As_agg[lane * 4 + 3][ln] = acc.w;
    }
    __syncthreads();

    // ---------- Phase 2: GEMM ----------
    int tx = t & 15;      // output group (4 outs)
    int ty = t >> 4;      // node group (4 nodes)
    int kq = (t & 7) * 4; // k offset within chunk (0..28)
    int row = t >> 3;     // 0..31

    float acc[4][4];
#pragma unroll
    for (int i = 0; i < 4; i++)
#pragma unroll
        for (int j = 0; j < 4; j++) acc[i][j] = 0.f;

    for (int kb = 0; kb < 256; kb += 32) {
        const float* Wsrc = (kb < 128) ? (Wl + kb) : (Wr + (kb - 128));

#pragma unroll
        for (int r2 = 0; r2 < 2; r2++) {
            // weight tile (every kb)
            int c = row + r2 * 32;
            float4 wv = *(const float4*)(Wsrc + (size_t)c * D_IN + kq);
            Bs[kq + 0][c] = wv.x;
            Bs[kq + 1][c] = wv.y;
            Bs[kq + 2][c] = wv.z;
            Bs[kq + 3][c] = wv.w;

            // x tile (only for the second K half), staged into consumed rows
            if (kb >= 128) {
                int n = nb + row + r2 * 32;
                float4 v = (n < N)
                    ? *(const float4*)(x + (size_t)n * D_IN + (kb - 128) + kq)
                    : make_float4(0.f, 0.f, 0.f, 0.f);
                int kr = (kb - 128) + kq;
                As_agg[kr + 0][row + r2 * 32] = v.x;
                As_agg[kr + 1][row + r2 * 32] = v.y;
                As_agg[kr + 2][row + r2 * 32] = v.z;
                As_agg[kr + 3][row + r2 * 32] = v.w;
            }
        }
        __syncthreads();

        const float (*Arows)[65] = As_agg + (kb & 127);
#pragma unroll
        for (int kk = 0; kk < 32; kk++) {
            float a0 = Arows[kk][ty * 4 + 0];
            float a1 = Arows[kk][ty * 4 + 1];
            float a2 = Arows[kk][ty * 4 + 2];
            float a3 = Arows[kk][ty * 4 + 3];
            float b0 = Bs[kk][tx * 4 + 0];
            float b1 = Bs[kk][tx * 4 + 1];
            float b2 = Bs[kk][tx * 4 + 2];
            float b3 = Bs[kk][tx * 4 + 3];
            acc[0][0] += a0 * b0; acc[0][1] += a0 * b1; acc[0][2] += a0 * b2; acc[0][3] += a0 * b3;
            acc[1][0] += a1 * b0; acc[1][1] += a1 * b1; acc[1][2] += a1 * b2; acc[1][3] += a1 * b3;
            acc[2][0] += a2 * b0; acc[2][1] += a2 * b1; acc[2][2] += a2 * b2; acc[2][3] += a2 * b3;
            acc[3][0] += a3 * b0; acc[3][1] += a3 * b1; acc[3][2] += a3 * b2; acc[3][3] += a3 * b3;
        }
        __syncthreads();
    }

    // bias
    float bv[4];
#pragma unroll
    for (int j = 0; j < 4; j++) bv[j] = bl[tx * 4 + j];
#pragma unroll
    for (int i = 0; i < 4; i++)
#pragma unroll
        for (int j = 0; j < 4; j++) acc[i][j] += bv[j];

    // log_softmax per node row: the 64 outputs of node (nb + ty*4 + i) live
    // in the 16 lanes sharing this ty (one half-warp) -> shfl_xor 1,2,4,8.
#pragma unroll
    for (int i = 0; i < 4; i++) {
        float m = acc[i][0];
        m = fmaxf(m, acc[i][1]);
        m = fmaxf(m, acc[i][2]);
        m = fmaxf(m, acc[i][3]);
#pragma unroll
        for (int o = 8; o >= 1; o >>= 1)
            m = fmaxf(m, __shfl_xor_sync(0xffffffffu, m, o));
        float s = expf(acc[i][0] - m) + expf(acc[i][1] - m) +
                  expf(acc[i][2] - m) + expf(acc[i][3] - m);
#pragma unroll
        for (int o = 8; o >= 1; o >>= 1)
            s += __shfl_xor_sync(0xffffffffu, s, o);
        float lse = m + logf(s);

        int n = nb + ty * 4 + i;
        if (n < N) {
            float4 o4 = make_float4(acc[i][0] - lse, acc[i][1] - lse,
                                    acc[i][2] - lse, acc[i][3] - lse);
            *(float4*)(out + (size_t)n * D_OUT + tx * 4) = o4;
        }
    }
}

// ---------------- launcher -------------------------------------------------
extern "C" void kernel_launch(void* const* d_in, const int* in_sizes, int n_in,
                              void* d_out, int out_size) {
    const float* x  = (const float*)d_in[0];
    const void*  ei = d_in[1];
    const float* Wl = (const float*)d_in[2];
    const float* bl = (const float*)d_in[3];
    const float* Wr = (const float*)d_in[4];
    float* out = (float*)d_out;

    int N = in_sizes[0] / D_IN;
    int E = in_sizes[1] / 2;
    int nb = (N + 1023) / 1024;

    k_detect<<<1, 32>>>((const unsigned int*)ei);
    k_zero<<<(N + 255) / 256, 256>>>(N);
    k_count<<<(E + 255) / 256, 256>>>(ei, E);
    k_scan1<<<nb, 1024>>>(N);
    k_scan2<<<1, 128>>>(nb);
    k_scan3<<<(N + 255) / 256, 256>>>(N, E);
    k_scatter<<<(E + 255) / 256, 256>>>(E);
    k_aggemm<<<(N + 63) / 64, 256>>>(x, Wl, bl, Wr, out, N);
}